// round 2
// baseline (speedup 1.0000x reference)
#include <cuda_runtime.h>
#include <math.h>
#include <stdint.h>

// ---------------------------------------------------------------------------
// MemNetE2E: sim = (q/||q||)·(k/||k||)^T ; top5 per query ; gather outputs.
// Round 1: exact-fp32 baseline, FIXED Qs chunk indexing (kk + k).
// GEMM via packed fma.rn.f32x2 (FFMA2), fused per-CTA top-5 over 64 key
// splits, then merge kernel.
// ---------------------------------------------------------------------------

#define EPSF    1e-8f
#define TOPK    5
#define NSPLIT  64
#define BM      128
#define BN      128
#define BKC     32          // K chunk
#define QS_STRIDE 130       // 128 + 2 pad (even -> 8B-aligned float2 rows)
#define KS_STRIDE 130
#define SS_STRIDE 129

#define MAXB 1024
#define MAXS 65536

__device__ float g_rq[MAXB];
__device__ float g_rk[MAXS];
__device__ float g_cval[MAXB * NSPLIT * TOPK];
__device__ int   g_cidx[MAXB * NSPLIT * TOPK];

__device__ __forceinline__ unsigned long long dup2(unsigned int x) {
    unsigned long long r;
    asm("mov.b64 %0, {%1, %1};" : "=l"(r) : "r"(x));
    return r;
}
#define FMA2(accv, av, bv) \
    asm("fma.rn.f32x2 %0, %1, %2, %0;" : "+l"(accv) : "l"(av), "l"(bv))

// ---- reciprocal row norms: rnorm[r] = 1 / max(||X[r,:]||, EPS) --------------
__global__ void norm_kernel(const float* __restrict__ X,
                            float* __restrict__ rnorm, int rows, int D) {
    int warp = (blockIdx.x * blockDim.x + threadIdx.x) >> 5;
    int lane = threadIdx.x & 31;
    if (warp >= rows) return;
    const float4* row = (const float4*)(X + (size_t)warp * D);
    float ss = 0.f;
    for (int i = lane; i < (D >> 2); i += 32) {
        float4 v = row[i];
        ss += v.x * v.x + v.y * v.y + v.z * v.z + v.w * v.w;
    }
    #pragma unroll
    for (int o = 16; o; o >>= 1) ss += __shfl_xor_sync(0xffffffffu, ss, o);
    if (lane == 0) rnorm[warp] = 1.0f / fmaxf(sqrtf(ss), EPSF);
}

// ---- new_ages base copy -----------------------------------------------------
__global__ void copy_ages_kernel(const float* __restrict__ a,
                                 float* __restrict__ o, int S) {
    int i = blockIdx.x * blockDim.x + threadIdx.x;
    if (i < S) o[i] = a[i];
}

// ---- main GEMM + fused per-split top-5 -------------------------------------
// grid = (B/BM, NSPLIT), 256 threads. D must be 256.
__global__ __launch_bounds__(256, 1)
void gemm_topk_kernel(const float* __restrict__ Q, const float* __restrict__ Kx,
                      int B, int S) {
    extern __shared__ float sm[];
    float* Qs = sm;                              // [256][QS_STRIDE]
    float* Ks = Qs + 256 * QS_STRIDE;            // [BKC][KS_STRIDE]
    float* Ss = Ks + BKC * KS_STRIDE;            // [BM][SS_STRIDE]

    const int tid = threadIdx.x;
    const int tx  = tid & 15;                    // n-direction (16)
    const int ty  = tid >> 4;                    // m-direction (16)
    const int m0g = blockIdx.x * BM;
    const int splitKeys = S / NSPLIT;
    const int ntiles    = splitKeys / BN;
    const int sbase     = blockIdx.y * splitKeys;

    // Load Q tile transposed: Qs[k][m] = Q[m0g+m][k]
    #pragma unroll
    for (int i = 0; i < (BM * 256 / 4) / 256; i++) {   // 32 iters
        int f4 = tid + i * 256;
        int m  = f4 >> 6;                              // 64 float4 per row
        int c4 = f4 & 63;
        float4 v = *(const float4*)(Q + (size_t)(m0g + m) * 256 + c4 * 4);
        int k = c4 * 4;
        Qs[(k + 0) * QS_STRIDE + m] = v.x;
        Qs[(k + 1) * QS_STRIDE + m] = v.y;
        Qs[(k + 2) * QS_STRIDE + m] = v.z;
        Qs[(k + 3) * QS_STRIDE + m] = v.w;
    }

    float rqv[8];
    #pragma unroll
    for (int i = 0; i < 8; i++) rqv[i] = g_rq[m0g + (ty << 3) + i];

    // running top-5 for owner threads (tid<128 owns local query row tid)
    float tv0 = -INFINITY, tv1 = -INFINITY, tv2 = -INFINITY,
          tv3 = -INFINITY, tv4 = -INFINITY;
    int   ti0 = 0, ti1 = 0, ti2 = 0, ti3 = 0, ti4 = 0;

    for (int t = 0; t < ntiles; t++) {
        const int nbase = sbase + t * BN;

        unsigned long long acc[4][8];
        #pragma unroll
        for (int p = 0; p < 4; p++)
            #pragma unroll
            for (int j = 0; j < 8; j++) acc[p][j] = 0ull;

        for (int kk = 0; kk < 256; kk += BKC) {
            // load K chunk transposed: Ks[k][n] = K[nbase+n][kk+k]
            #pragma unroll
            for (int i = 0; i < (BN * BKC / 4) / 256; i++) {  // 4 iters
                int f4 = tid + i * 256;
                int n  = f4 >> 3;                  // 8 float4 per row chunk
                int c4 = f4 & 7;
                float4 v = *(const float4*)(Kx + (size_t)(nbase + n) * 256 + kk + c4 * 4);
                int k = c4 * 4;
                Ks[(k + 0) * KS_STRIDE + n] = v.x;
                Ks[(k + 1) * KS_STRIDE + n] = v.y;
                Ks[(k + 2) * KS_STRIDE + n] = v.z;
                Ks[(k + 3) * KS_STRIDE + n] = v.w;
            }
            __syncthreads();

            #pragma unroll 8
            for (int k = 0; k < BKC; k++) {
                const float* qp = Qs + (kk + k) * QS_STRIDE + (ty << 3);  // FIXED
                const float* kp = Ks + k * KS_STRIDE + (tx << 1);
                unsigned long long a0 = *(const unsigned long long*)(qp + 0);
                unsigned long long a1 = *(const unsigned long long*)(qp + 2);
                unsigned long long a2 = *(const unsigned long long*)(qp + 4);
                unsigned long long a3 = *(const unsigned long long*)(qp + 6);
                unsigned long long b0 = *(const unsigned long long*)(kp + 0);
                unsigned long long b1 = *(const unsigned long long*)(kp + 32);
                unsigned long long b2 = *(const unsigned long long*)(kp + 64);
                unsigned long long b3 = *(const unsigned long long*)(kp + 96);
                unsigned long long d0 = dup2((unsigned)b0);
                unsigned long long d1 = dup2((unsigned)(b0 >> 32));
                unsigned long long d2 = dup2((unsigned)b1);
                unsigned long long d3 = dup2((unsigned)(b1 >> 32));
                unsigned long long d4 = dup2((unsigned)b2);
                unsigned long long d5 = dup2((unsigned)(b2 >> 32));
                unsigned long long d6 = dup2((unsigned)b3);
                unsigned long long d7 = dup2((unsigned)(b3 >> 32));
                #pragma unroll
                for (int p = 0; p < 4; p++) {
                    unsigned long long a = (p == 0) ? a0 : (p == 1) ? a1
                                         : (p == 2) ? a2 : a3;
                    FMA2(acc[p][0], a, d0);
                    FMA2(acc[p][1], a, d1);
                    FMA2(acc[p][2], a, d2);
                    FMA2(acc[p][3], a, d3);
                    FMA2(acc[p][4], a, d4);
                    FMA2(acc[p][5], a, d5);
                    FMA2(acc[p][6], a, d6);
                    FMA2(acc[p][7], a, d7);
                }
            }
            __syncthreads();
        }

        // epilogue: scale by rq*rk, stage to Ss
        float rkv[8];
        #pragma unroll
        for (int jj = 0; jj < 4; jj++) {
            rkv[2 * jj]     = g_rk[nbase + (tx << 1) + 32 * jj];
            rkv[2 * jj + 1] = g_rk[nbase + (tx << 1) + 32 * jj + 1];
        }
        #pragma unroll
        for (int p = 0; p < 4; p++) {
            int mrow = (ty << 3) + 2 * p;
            float rq0 = rqv[2 * p], rq1 = rqv[2 * p + 1];
            #pragma unroll
            for (int j = 0; j < 8; j++) {
                int ncol = (tx << 1) + 32 * (j >> 1) + (j & 1);
                float lo = __uint_as_float((unsigned)acc[p][j]);
                float hi = __uint_as_float((unsigned)(acc[p][j] >> 32));
                float rkn = rkv[j];
                Ss[mrow * SS_STRIDE + ncol]       = lo * rq0 * rkn;
                Ss[(mrow + 1) * SS_STRIDE + ncol] = hi * rq1 * rkn;
            }
        }
        __syncthreads();

        // owner threads update running top-5 for their query
        if (tid < BM) {
            const float* row = Ss + tid * SS_STRIDE;
            #pragma unroll 4
            for (int n = 0; n < BN; n++) {
                float v = row[n];
                if (v > tv4) {
                    int gi = nbase + n;
                    if (v > tv0) {
                        tv4=tv3; ti4=ti3; tv3=tv2; ti3=ti2; tv2=tv1; ti2=ti1;
                        tv1=tv0; ti1=ti0; tv0=v; ti0=gi;
                    } else if (v > tv1) {
                        tv4=tv3; ti4=ti3; tv3=tv2; ti3=ti2; tv2=tv1; ti2=ti1;
                        tv1=v; ti1=gi;
                    } else if (v > tv2) {
                        tv4=tv3; ti4=ti3; tv3=tv2; ti3=ti2; tv2=v; ti2=gi;
                    } else if (v > tv3) {
                        tv4=tv3; ti4=ti3; tv3=v; ti3=gi;
                    } else {
                        tv4=v; ti4=gi;
                    }
                }
            }
        }
        __syncthreads();
    }

    if (tid < BM) {
        int q = m0g + tid;
        int base = (q * NSPLIT + blockIdx.y) * TOPK;
        g_cval[base + 0] = tv0; g_cidx[base + 0] = ti0;
        g_cval[base + 1] = tv1; g_cidx[base + 1] = ti1;
        g_cval[base + 2] = tv2; g_cidx[base + 2] = ti2;
        g_cval[base + 3] = tv3; g_cidx[base + 3] = ti3;
        g_cval[base + 4] = tv4; g_cidx[base + 4] = ti4;
    }
}

// ---- merge splits + produce all outputs ------------------------------------
__global__ void merge_out_kernel(const float* __restrict__ values,
                                 const float* __restrict__ errors,
                                 const float* __restrict__ ages,
                                 float* __restrict__ outC,
                                 float* __restrict__ outE,
                                 float* __restrict__ outS,
                                 float* __restrict__ outA,
                                 int V) {
    __shared__ float sv[NSPLIT * TOPK];
    __shared__ int   si[NSPLIT * TOPK];
    __shared__ int   bi[TOPK];
    const int q = blockIdx.x;
    const int tid = threadIdx.x;
    const int base = q * NSPLIT * TOPK;
    for (int i = tid; i < NSPLIT * TOPK; i += blockDim.x) {
        sv[i] = g_cval[base + i];
        si[i] = g_cidx[base + i];
    }
    __syncthreads();
    if (tid == 0) {
        float v0=-INFINITY,v1=-INFINITY,v2=-INFINITY,v3=-INFINITY,v4=-INFINITY;
        int   i0=0,i1=0,i2=0,i3=0,i4=0;
        for (int i = 0; i < NSPLIT * TOPK; i++) {
            float v = sv[i];
            if (v > v4) {
                int gi = si[i];
                if (v > v0)      { v4=v3;i4=i3; v3=v2;i3=i2; v2=v1;i2=i1; v1=v0;i1=i0; v0=v;i0=gi; }
                else if (v > v1) { v4=v3;i4=i3; v3=v2;i3=i2; v2=v1;i2=i1; v1=v;i1=gi; }
                else if (v > v2) { v4=v3;i4=i3; v3=v2;i3=i2; v2=v;i2=gi; }
                else if (v > v3) { v4=v3;i4=i3; v3=v;i3=gi; }
                else             { v4=v; i4=gi; }
            }
        }
        bi[0]=i0; bi[1]=i1; bi[2]=i2; bi[3]=i3; bi[4]=i4;
        outE[q] = (errors[i0]+errors[i1]+errors[i2]+errors[i3]+errors[i4]) * 0.2f;
        outS[q] = v0;
    }
    __syncthreads();
    for (int c = tid; c < V; c += blockDim.x) {
        float a = 0.f;
        #pragma unroll
        for (int j = 0; j < TOPK; j++)
            a += values[(size_t)bi[j] * V + c];
        outC[(size_t)q * V + c] = a * 0.2f;
    }
    if (tid < TOPK) {
        int ix = bi[tid];
        outA[ix] = ages[ix] + 1.0f;   // all writers of a slot write identical value
    }
}

// ---------------------------------------------------------------------------
extern "C" void kernel_launch(void* const* d_in, const int* in_sizes, int n_in,
                              void* d_out, int out_size) {
    const float* Q  = (const float*)d_in[0];
    const float* Kx = (const float*)d_in[1];
    const float* Vx = (const float*)d_in[2];
    const float* E  = (const float*)d_in[3];
    const float* A  = (const float*)d_in[4];

    const int S = in_sizes[3];              // errors: (S,)
    const int D = in_sizes[1] / S;          // keys:   (S, D)
    const int V = in_sizes[2] / S;          // values: (S, V)
    const int B = in_sizes[0] / D;          // query:  (B, D)

    float* out  = (float*)d_out;
    float* outC = out;                      // (B, V)
    float* outE = outC + (size_t)B * V;     // (B,)
    float* outS = outE + B;                 // (B,)
    float* outA = outS + B;                 // (S,)

    float *rq = nullptr, *rk = nullptr;
    cudaGetSymbolAddress((void**)&rq, g_rq);
    cudaGetSymbolAddress((void**)&rk, g_rk);

    norm_kernel<<<(B + 7) / 8, 256>>>(Q, rq, B, D);
    norm_kernel<<<(S + 7) / 8, 256>>>(Kx, rk, S, D);
    copy_ages_kernel<<<(S + 255) / 256, 256>>>(A, outA, S);

    size_t smemB = (size_t)(256 * QS_STRIDE + BKC * KS_STRIDE + BM * SS_STRIDE)
                   * sizeof(float);
    cudaFuncSetAttribute(gemm_topk_kernel,
                         cudaFuncAttributeMaxDynamicSharedMemorySize,
                         (int)smemB);
    dim3 grid(B / BM, NSPLIT);
    gemm_topk_kernel<<<grid, 256, smemB>>>(Q, Kx, B, S);

    merge_out_kernel<<<B, 256>>>(Vx, E, A, outC, outE, outS, outA, V);
    (void)n_in; (void)out_size;
}

// round 7
// speedup vs baseline: 2.4772x; 2.4772x over previous
#include <cuda_runtime.h>
#include <cuda_bf16.h>
#include <math.h>
#include <stdint.h>

// ---------------------------------------------------------------------------
// MemNetE2E round 6: round-4 HMMA design, resubmitted after two infra
// failures. Change vs round 4: score-stage buffer aliased onto the B-tile
// buffer (identical 67584-byte size, disjoint lifetimes enforced by an added
// __syncthreads) -> smem 198KB -> 132KB. Algorithm unchanged.
//   K1: normalize rows -> rq/rk + bf16 normalized copies g_qn/g_kn
//   K2: HMMA GEMM (128x128 tile, K=256) + fused per-split top-8 shortlist
//       (ranks q_hat.k_hat directly -- no rk rescale; round-3 bug fixed)
//   K3: merge 256 cands/query -> approx top-16 -> exact fp32 rescore -> top-5
// ---------------------------------------------------------------------------

#define EPSF   1e-8f
#define TOPK   5
#define CAND   8
#define RESC   16
#define NSPLIT 32
#define BM     128
#define BN     128
#define DDIM   256
#define MAXB   1024
#define MAXS   65536

// padded smem rows: 256 bf16 + 8 pad = 264 bf16 = 528 bytes
#define RB     528
// score stage row: 132 floats (128*132*4 == 128*RB exactly)
#define SSW    132

__device__ float          g_rq[MAXB];
__device__ float          g_rk[MAXS];
__device__ __nv_bfloat16  g_qn[MAXB * DDIM];
__device__ __nv_bfloat16  g_kn[MAXS * DDIM];
__device__ float          g_cval[MAXB * NSPLIT * CAND];
__device__ int            g_cidx[MAXB * NSPLIT * CAND];

__device__ __forceinline__ uint32_t smem_u32(const void* p) {
    uint32_t a;
    asm("{ .reg .u64 t; cvta.to.shared.u64 t, %1; cvt.u32.u64 %0, t; }"
        : "=r"(a) : "l"(p));
    return a;
}
#define LDSM_X4(r, addr)                                                      \
    asm volatile("ldmatrix.sync.aligned.m8n8.x4.shared.b16 {%0,%1,%2,%3}, [%4];" \
        : "=r"((r)[0]), "=r"((r)[1]), "=r"((r)[2]), "=r"((r)[3]) : "r"(addr))
#define MMA16816(c, a, b0, b1)                                                \
    asm volatile("mma.sync.aligned.m16n8k16.row.col.f32.bf16.bf16.f32 "       \
        "{%0,%1,%2,%3}, {%4,%5,%6,%7}, {%8,%9}, {%0,%1,%2,%3};"               \
        : "+f"((c)[0]), "+f"((c)[1]), "+f"((c)[2]), "+f"((c)[3])              \
        : "r"((a)[0]), "r"((a)[1]), "r"((a)[2]), "r"((a)[3]),                 \
          "r"(b0), "r"(b1))

// ---------------- K1: normalize rows -> rnorm + bf16 normalized copy --------
__global__ void normalize_kernel(const float* __restrict__ X,
                                 float* __restrict__ rn,
                                 __nv_bfloat16* __restrict__ XN, int rows) {
    int warp = (blockIdx.x * blockDim.x + threadIdx.x) >> 5;
    int lane = threadIdx.x & 31;
    if (warp >= rows) return;
    const float4* row = (const float4*)(X + (size_t)warp * DDIM);
    float4 a = row[lane];
    float4 b = row[lane + 32];
    float ss = a.x * a.x + a.y * a.y + a.z * a.z + a.w * a.w
             + b.x * b.x + b.y * b.y + b.z * b.z + b.w * b.w;
    #pragma unroll
    for (int o = 16; o; o >>= 1) ss += __shfl_xor_sync(0xffffffffu, ss, o);
    float r = 1.0f / fmaxf(sqrtf(ss), EPSF);
    __nv_bfloat162 p0 = __floats2bfloat162_rn(a.x * r, a.y * r);
    __nv_bfloat162 p1 = __floats2bfloat162_rn(a.z * r, a.w * r);
    __nv_bfloat162 p2 = __floats2bfloat162_rn(b.x * r, b.y * r);
    __nv_bfloat162 p3 = __floats2bfloat162_rn(b.z * r, b.w * r);
    uint2* out = (uint2*)(XN + (size_t)warp * DDIM);
    uint2 u0, u1;
    u0.x = *(uint32_t*)&p0; u0.y = *(uint32_t*)&p1;
    u1.x = *(uint32_t*)&p2; u1.y = *(uint32_t*)&p3;
    out[lane] = u0;
    out[lane + 32] = u1;
    if (lane == 0) rn[warp] = r;
}

__global__ void copy_ages_kernel(const float* __restrict__ a,
                                 float* __restrict__ o, int S) {
    int i = blockIdx.x * blockDim.x + threadIdx.x;
    if (i < S) o[i] = a[i];
}

// copy a 128x256-bf16 tile into padded smem rows (RB bytes per row)
__device__ __forceinline__ void store_tile_pad(char* dst,
                                               const uint4* __restrict__ src,
                                               int tid) {
    #pragma unroll
    for (int i = 0; i < 16; i++) {
        int idx = tid + i * 256;               // 4096 uint4 total
        int row = idx >> 5;                    // 32 uint4 per row
        int c   = idx & 31;
        *(uint4*)(dst + row * RB + c * 16) = src[idx];
    }
}

__device__ __forceinline__ void ins8(float v, int gi, float tv[CAND], int ti[CAND]) {
    if (v <= tv[CAND - 1]) return;
    tv[CAND - 1] = v; ti[CAND - 1] = gi;
    #pragma unroll
    for (int p = CAND - 1; p > 0; p--) {
        if (tv[p] > tv[p - 1]) {
            float f = tv[p - 1]; tv[p - 1] = tv[p]; tv[p] = f;
            int   g = ti[p - 1]; ti[p - 1] = ti[p]; ti[p] = g;
        }
    }
}

// ---------------- K2: HMMA GEMM + per-split top-8 ---------------------------
// smem map (bytes):  A: [0, 128*RB) | B / score-stage (aliased): [+128*RB)
#define A_OFF   0
#define B_OFF   (128 * RB)
#define SMEM_SZ (2 * 128 * RB)

__global__ void __launch_bounds__(256, 1)
gemm_shortlist_kernel(int S) {
    extern __shared__ char sm[];
    const uint32_t smb = smem_u32(sm);
    float* Ssf = (float*)(sm + B_OFF);   // aliases the B tile (disjoint lifetime)

    const int tid  = threadIdx.x;
    const int wid  = tid >> 5;
    const int lane = tid & 31;
    const int wm   = wid >> 2;          // 0..1 (m half)
    const int wn   = wid & 3;           // 0..3 (n quarter)
    const int gid  = lane >> 2;
    const int tig  = lane & 3;

    const int m0        = blockIdx.x * BM;
    const int split     = blockIdx.y;
    const int splitKeys = S / NSPLIT;          // 2048
    const int T         = splitKeys / BN;      // 16
    const int sbase     = split * splitKeys;

    // resident A tile
    store_tile_pad(sm + A_OFF, (const uint4*)(g_qn + (size_t)m0 * DDIM), tid);

    // ldmatrix lane address offsets
    const int arow = (lane & 7) + ((lane >> 3) & 1) * 8;  // row within m16
    const int acol = (lane >> 4) * 8;                     // k half
    uint32_t aBase[4];
    #pragma unroll
    for (int mi = 0; mi < 4; mi++)
        aBase[mi] = smb + A_OFF + (uint32_t)((wm * 64 + mi * 16 + arow) * RB + acol * 2);

    const int brow = (lane & 7) + ((lane >> 4) & 1) * 8;  // n within n16 pair
    const int bcol = ((lane >> 3) & 1) * 8;               // k half
    uint32_t bBase[2];
    #pragma unroll
    for (int np = 0; np < 2; np++)
        bBase[np] = smb + B_OFF + (uint32_t)((wn * 32 + np * 16 + brow) * RB + bcol * 2);

    float tv[CAND]; int ti[CAND];
    #pragma unroll
    for (int i = 0; i < CAND; i++) { tv[i] = -INFINITY; ti[i] = 0; }

    for (int t = 0; t < T; t++) {
        const int nbase = sbase + t * BN;
        store_tile_pad(sm + B_OFF, (const uint4*)(g_kn + (size_t)nbase * DDIM), tid);
        __syncthreads();

        float acc[4][4][4];
        #pragma unroll
        for (int mi = 0; mi < 4; mi++)
            #pragma unroll
            for (int ni = 0; ni < 4; ni++)
                #pragma unroll
                for (int e = 0; e < 4; e++) acc[mi][ni][e] = 0.f;

        #pragma unroll 4
        for (int ks = 0; ks < 16; ks++) {
            const uint32_t koff = (uint32_t)(ks * 16 * 2);
            uint32_t a[4][4], b[2][4];
            #pragma unroll
            for (int mi = 0; mi < 4; mi++) LDSM_X4(a[mi], aBase[mi] + koff);
            #pragma unroll
            for (int np = 0; np < 2; np++) LDSM_X4(b[np], bBase[np] + koff);
            #pragma unroll
            for (int mi = 0; mi < 4; mi++) {
                #pragma unroll
                for (int ni = 0; ni < 4; ni++) {
                    uint32_t b0 = b[ni >> 1][(ni & 1) * 2];
                    uint32_t b1 = b[ni >> 1][(ni & 1) * 2 + 1];
                    MMA16816(acc[mi][ni], a[mi], b0, b1);
                }
            }
        }
        __syncthreads();   // all warps done reading B before scores overwrite it

        // stage scores (q_hat . k_hat -- already normalized, no extra scale)
        #pragma unroll
        for (int mi = 0; mi < 4; mi++) {
            #pragma unroll
            for (int ni = 0; ni < 4; ni++) {
                int row0 = wm * 64 + mi * 16 + gid;
                int col  = wn * 32 + ni * 8 + tig * 2;
                *(float2*)(Ssf + row0 * SSW + col) =
                    make_float2(acc[mi][ni][0], acc[mi][ni][1]);
                *(float2*)(Ssf + (row0 + 8) * SSW + col) =
                    make_float2(acc[mi][ni][2], acc[mi][ni][3]);
            }
        }
        __syncthreads();

        // owner threads: per-query running top-8 (rank by raw cosine score)
        if (tid < BM) {
            const float4* rowp = (const float4*)(Ssf + tid * SSW);
            #pragma unroll 4
            for (int j = 0; j < 32; j++) {
                float4 v = rowp[j];
                int gi = nbase + j * 4;
                ins8(v.x, gi + 0, tv, ti);
                ins8(v.y, gi + 1, tv, ti);
                ins8(v.z, gi + 2, tv, ti);
                ins8(v.w, gi + 3, tv, ti);
            }
        }
        __syncthreads();   // scan done before next tile's B load overwrites
    }

    if (tid < BM) {
        int q = m0 + tid;
        int base = (q * NSPLIT + split) * CAND;
        #pragma unroll
        for (int i = 0; i < CAND; i++) {
            g_cval[base + i] = tv[i];
            g_cidx[base + i] = ti[i];
        }
    }
}

// ---------------- K3: merge -> exact rescore -> outputs ---------------------
__global__ void merge_out_kernel(const float* __restrict__ Q,
                                 const float* __restrict__ Kx,
                                 const float* __restrict__ values,
                                 const float* __restrict__ errors,
                                 const float* __restrict__ ages,
                                 float* __restrict__ outC,
                                 float* __restrict__ outE,
                                 float* __restrict__ outS,
                                 float* __restrict__ outA, int V) {
    __shared__ float sv[NSPLIT * CAND];
    __shared__ int   si[NSPLIT * CAND];
    __shared__ float b16v[RESC];
    __shared__ int   b16i[RESC];
    __shared__ float se[RESC];
    __shared__ int   bi[TOPK];
    const int q = blockIdx.x;
    const int tid = threadIdx.x;
    const int wid = tid >> 5;
    const int lane = tid & 31;

    sv[tid] = g_cval[q * NSPLIT * CAND + tid];
    si[tid] = g_cidx[q * NSPLIT * CAND + tid];
    __syncthreads();

    if (tid == 0) {   // serial approx top-16 of 256
        for (int i = 0; i < RESC; i++) { b16v[i] = -INFINITY; b16i[i] = 0; }
        for (int i = 0; i < NSPLIT * CAND; i++) {
            float v = sv[i];
            if (v > b16v[RESC - 1]) {
                b16v[RESC - 1] = v; b16i[RESC - 1] = si[i];
                for (int p = RESC - 1; p > 0 && b16v[p] > b16v[p - 1]; p--) {
                    float f = b16v[p - 1]; b16v[p - 1] = b16v[p]; b16v[p] = f;
                    int   g = b16i[p - 1]; b16i[p - 1] = b16i[p]; b16i[p] = g;
                }
            }
        }
    }
    __syncthreads();

    // exact fp32 rescore: 8 warps x 2 candidates
    #pragma unroll
    for (int r = 0; r < 2; r++) {
        int c = wid * 2 + r;
        int idx = b16i[c];
        const float4* qr = (const float4*)(Q + (size_t)q * DDIM);
        const float4* kr = (const float4*)(Kx + (size_t)idx * DDIM);
        float4 qa = qr[lane], qb = qr[lane + 32];
        float4 ka = kr[lane], kb = kr[lane + 32];
        float d = qa.x * ka.x + qa.y * ka.y + qa.z * ka.z + qa.w * ka.w
                + qb.x * kb.x + qb.y * kb.y + qb.z * kb.z + qb.w * kb.w;
        #pragma unroll
        for (int o = 16; o; o >>= 1) d += __shfl_xor_sync(0xffffffffu, d, o);
        if (lane == 0) se[c] = d * g_rq[q] * g_rk[idx];
    }
    __syncthreads();

    if (tid == 0) {   // exact top-5 of 16
        float bv[TOPK]; int bx[TOPK];
        for (int i = 0; i < TOPK; i++) { bv[i] = -INFINITY; bx[i] = 0; }
        for (int i = 0; i < RESC; i++) {
            float v = se[i];
            if (v > bv[TOPK - 1]) {
                bv[TOPK - 1] = v; bx[TOPK - 1] = b16i[i];
                for (int p = TOPK - 1; p > 0 && bv[p] > bv[p - 1]; p--) {
                    float f = bv[p - 1]; bv[p - 1] = bv[p]; bv[p] = f;
                    int   g = bx[p - 1]; bx[p - 1] = bx[p]; bx[p] = g;
                }
            }
        }
        for (int i = 0; i < TOPK; i++) bi[i] = bx[i];
        outE[q] = (errors[bx[0]] + errors[bx[1]] + errors[bx[2]]
                 + errors[bx[3]] + errors[bx[4]]) * 0.2f;
        outS[q] = bv[0];
    }
    __syncthreads();

    for (int c = tid; c < V; c += blockDim.x) {
        float a = 0.f;
        #pragma unroll
        for (int j = 0; j < TOPK; j++)
            a += values[(size_t)bi[j] * V + c];
        outC[(size_t)q * V + c] = a * 0.2f;
    }
    if (tid < TOPK) {
        int ix = bi[tid];
        outA[ix] = ages[ix] + 1.0f;   // identical value under races
    }
}

// ---------------------------------------------------------------------------
extern "C" void kernel_launch(void* const* d_in, const int* in_sizes, int n_in,
                              void* d_out, int out_size) {
    const float* Q  = (const float*)d_in[0];
    const float* Kx = (const float*)d_in[1];
    const float* Vx = (const float*)d_in[2];
    const float* E  = (const float*)d_in[3];
    const float* A  = (const float*)d_in[4];

    const int S = in_sizes[3];
    const int D = in_sizes[1] / S;
    const int V = in_sizes[2] / S;
    const int B = in_sizes[0] / D;

    float* out  = (float*)d_out;
    float* outC = out;
    float* outE = outC + (size_t)B * V;
    float* outS = outE + B;
    float* outA = outS + B;

    float *rq, *rk;
    __nv_bfloat16 *qn, *kn;
    cudaGetSymbolAddress((void**)&rq, g_rq);
    cudaGetSymbolAddress((void**)&rk, g_rk);
    cudaGetSymbolAddress((void**)&qn, g_qn);
    cudaGetSymbolAddress((void**)&kn, g_kn);

    normalize_kernel<<<(B + 7) / 8, 256>>>(Q, rq, qn, B);
    normalize_kernel<<<(S + 7) / 8, 256>>>(Kx, rk, kn, S);
    copy_ages_kernel<<<(S + 255) / 256, 256>>>(A, outA, S);

    cudaFuncSetAttribute(gemm_shortlist_kernel,
                         cudaFuncAttributeMaxDynamicSharedMemorySize, SMEM_SZ);
    dim3 grid(B / BM, NSPLIT);
    gemm_shortlist_kernel<<<grid, 256, SMEM_SZ>>>(S);

    merge_out_kernel<<<B, 256>>>(Q, Kx, Vx, E, A, outC, outE, outS, outA, V);
    (void)n_in; (void)out_size;
}

// round 8
// speedup vs baseline: 3.1554x; 1.2738x over previous
#include <cuda_runtime.h>
#include <cuda_bf16.h>
#include <math.h>
#include <stdint.h>

// ---------------------------------------------------------------------------
// MemNetE2E round 7: 2 CTAs/SM for phase overlap.
//   vs round 6: BM 128->64 (smem/CTA 132KB->99KB -> occupancy 2 CTAs/SM),
//   NSPLIT 32->16 (grid still 256 CTAs, ~one co-resident wave),
//   scan split across 2 threads/row (two half-row top-8s per split).
//   K1: normalize rows -> rq/rk + bf16 normalized copies g_qn/g_kn
//   K2: HMMA GEMM (64x128 tile, K=256) + fused per-split shortlist
//   K3: merge 256 cands/query -> approx top-16 -> exact fp32 rescore -> top-5
// ---------------------------------------------------------------------------

#define EPSF   1e-8f
#define TOPK   5
#define CAND   8          // per half-row shortlist depth
#define RESC   16
#define NSPLIT 16
#define CPQ    256        // candidates per query = NSPLIT * 2 * CAND
#define BM     64
#define BN     128
#define DDIM   256
#define MAXB   1024
#define MAXS   65536

// padded smem rows: 256 bf16 + 8 pad = 264 bf16 = 528 bytes
#define RB     528
// score stage row: 132 floats
#define SSW    132

__device__ float          g_rq[MAXB];
__device__ float          g_rk[MAXS];
__device__ __nv_bfloat16  g_qn[MAXB * DDIM];
__device__ __nv_bfloat16  g_kn[MAXS * DDIM];
__device__ float          g_cval[MAXB * CPQ];
__device__ int            g_cidx[MAXB * CPQ];

__device__ __forceinline__ uint32_t smem_u32(const void* p) {
    uint32_t a;
    asm("{ .reg .u64 t; cvta.to.shared.u64 t, %1; cvt.u32.u64 %0, t; }"
        : "=r"(a) : "l"(p));
    return a;
}
#define LDSM_X4(r, addr)                                                      \
    asm volatile("ldmatrix.sync.aligned.m8n8.x4.shared.b16 {%0,%1,%2,%3}, [%4];" \
        : "=r"((r)[0]), "=r"((r)[1]), "=r"((r)[2]), "=r"((r)[3]) : "r"(addr))
#define MMA16816(c, a, b0, b1)                                                \
    asm volatile("mma.sync.aligned.m16n8k16.row.col.f32.bf16.bf16.f32 "       \
        "{%0,%1,%2,%3}, {%4,%5,%6,%7}, {%8,%9}, {%0,%1,%2,%3};"               \
        : "+f"((c)[0]), "+f"((c)[1]), "+f"((c)[2]), "+f"((c)[3])              \
        : "r"((a)[0]), "r"((a)[1]), "r"((a)[2]), "r"((a)[3]),                 \
          "r"(b0), "r"(b1))

// ---------------- K1: normalize rows -> rnorm + bf16 normalized copy --------
__global__ void normalize_kernel(const float* __restrict__ X,
                                 float* __restrict__ rn,
                                 __nv_bfloat16* __restrict__ XN, int rows) {
    int warp = (blockIdx.x * blockDim.x + threadIdx.x) >> 5;
    int lane = threadIdx.x & 31;
    if (warp >= rows) return;
    const float4* row = (const float4*)(X + (size_t)warp * DDIM);
    float4 a = row[lane];
    float4 b = row[lane + 32];
    float ss = a.x * a.x + a.y * a.y + a.z * a.z + a.w * a.w
             + b.x * b.x + b.y * b.y + b.z * b.z + b.w * b.w;
    #pragma unroll
    for (int o = 16; o; o >>= 1) ss += __shfl_xor_sync(0xffffffffu, ss, o);
    float r = 1.0f / fmaxf(sqrtf(ss), EPSF);
    __nv_bfloat162 p0 = __floats2bfloat162_rn(a.x * r, a.y * r);
    __nv_bfloat162 p1 = __floats2bfloat162_rn(a.z * r, a.w * r);
    __nv_bfloat162 p2 = __floats2bfloat162_rn(b.x * r, b.y * r);
    __nv_bfloat162 p3 = __floats2bfloat162_rn(b.z * r, b.w * r);
    uint2* out = (uint2*)(XN + (size_t)warp * DDIM);
    uint2 u0, u1;
    u0.x = *(uint32_t*)&p0; u0.y = *(uint32_t*)&p1;
    u1.x = *(uint32_t*)&p2; u1.y = *(uint32_t*)&p3;
    out[lane] = u0;
    out[lane + 32] = u1;
    if (lane == 0) rn[warp] = r;
}

__global__ void copy_ages_kernel(const float* __restrict__ a,
                                 float* __restrict__ o, int S) {
    int i = blockIdx.x * blockDim.x + threadIdx.x;
    if (i < S) o[i] = a[i];
}

// copy an NROWSx256-bf16 tile into padded smem rows (RB bytes per row)
template <int NITER>
__device__ __forceinline__ void store_tile_pad(char* dst,
                                               const uint4* __restrict__ src,
                                               int tid) {
    #pragma unroll
    for (int i = 0; i < NITER; i++) {
        int idx = tid + i * 256;
        int row = idx >> 5;                    // 32 uint4 per row
        int c   = idx & 31;
        *(uint4*)(dst + row * RB + c * 16) = src[idx];
    }
}

__device__ __forceinline__ void ins8(float v, int gi, float tv[CAND], int ti[CAND]) {
    if (v <= tv[CAND - 1]) return;
    tv[CAND - 1] = v; ti[CAND - 1] = gi;
    #pragma unroll
    for (int p = CAND - 1; p > 0; p--) {
        if (tv[p] > tv[p - 1]) {
            float f = tv[p - 1]; tv[p - 1] = tv[p]; tv[p] = f;
            int   g = ti[p - 1]; ti[p - 1] = ti[p]; ti[p] = g;
        }
    }
}

// ---------------- K2: HMMA GEMM + per-split shortlist -----------------------
// smem map (bytes):  A: [0, 64*RB) | B / score-stage (aliased): [64*RB, +128*RB)
#define A_OFF   0
#define B_OFF   (64 * RB)
#define SMEM_SZ ((64 + 128) * RB)

__global__ void __launch_bounds__(256, 2)
gemm_shortlist_kernel(int S) {
    extern __shared__ char sm[];
    const uint32_t smb = smem_u32(sm);
    float* Ssf = (float*)(sm + B_OFF);   // aliases B tile (disjoint lifetime)

    const int tid  = threadIdx.x;
    const int wid  = tid >> 5;
    const int lane = tid & 31;
    const int wm   = wid >> 2;          // 0..1 (m half: 32 rows)
    const int wn   = wid & 3;           // 0..3 (n quarter: 32 cols)
    const int gid  = lane >> 2;
    const int tig  = lane & 3;

    const int m0        = blockIdx.x * BM;
    const int split     = blockIdx.y;
    const int splitKeys = S / NSPLIT;          // 4096
    const int T         = splitKeys / BN;      // 32
    const int sbase     = split * splitKeys;

    // resident A tile (64 rows)
    store_tile_pad<8>(sm + A_OFF, (const uint4*)(g_qn + (size_t)m0 * DDIM), tid);

    // ldmatrix lane address offsets
    const int arow = (lane & 7) + ((lane >> 3) & 1) * 8;  // row within m16
    const int acol = (lane >> 4) * 8;                     // k half
    uint32_t aBase[2];
    #pragma unroll
    for (int mi = 0; mi < 2; mi++)
        aBase[mi] = smb + A_OFF + (uint32_t)((wm * 32 + mi * 16 + arow) * RB + acol * 2);

    const int brow = (lane & 7) + ((lane >> 4) & 1) * 8;  // n within n16 pair
    const int bcol = ((lane >> 3) & 1) * 8;               // k half
    uint32_t bBase[2];
    #pragma unroll
    for (int np = 0; np < 2; np++)
        bBase[np] = smb + B_OFF + (uint32_t)((wn * 32 + np * 16 + brow) * RB + bcol * 2);

    float tv[CAND]; int ti[CAND];
    #pragma unroll
    for (int i = 0; i < CAND; i++) { tv[i] = -INFINITY; ti[i] = 0; }

    for (int t = 0; t < T; t++) {
        const int nbase = sbase + t * BN;
        store_tile_pad<16>(sm + B_OFF, (const uint4*)(g_kn + (size_t)nbase * DDIM), tid);
        __syncthreads();

        float acc[2][4][4];
        #pragma unroll
        for (int mi = 0; mi < 2; mi++)
            #pragma unroll
            for (int ni = 0; ni < 4; ni++)
                #pragma unroll
                for (int e = 0; e < 4; e++) acc[mi][ni][e] = 0.f;

        #pragma unroll 4
        for (int ks = 0; ks < 16; ks++) {
            const uint32_t koff = (uint32_t)(ks * 16 * 2);
            uint32_t a[2][4], b[2][4];
            #pragma unroll
            for (int mi = 0; mi < 2; mi++) LDSM_X4(a[mi], aBase[mi] + koff);
            #pragma unroll
            for (int np = 0; np < 2; np++) LDSM_X4(b[np], bBase[np] + koff);
            #pragma unroll
            for (int mi = 0; mi < 2; mi++) {
                #pragma unroll
                for (int ni = 0; ni < 4; ni++) {
                    uint32_t b0 = b[ni >> 1][(ni & 1) * 2];
                    uint32_t b1 = b[ni >> 1][(ni & 1) * 2 + 1];
                    MMA16816(acc[mi][ni], a[mi], b0, b1);
                }
            }
        }
        __syncthreads();   // all warps done reading B before scores overwrite it

        // stage scores (q_hat . k_hat -- pre-normalized, no extra scale)
        #pragma unroll
        for (int mi = 0; mi < 2; mi++) {
            #pragma unroll
            for (int ni = 0; ni < 4; ni++) {
                int row0 = wm * 32 + mi * 16 + gid;
                int col  = wn * 32 + ni * 8 + tig * 2;
                *(float2*)(Ssf + row0 * SSW + col) =
                    make_float2(acc[mi][ni][0], acc[mi][ni][1]);
                *(float2*)(Ssf + (row0 + 8) * SSW + col) =
                    make_float2(acc[mi][ni][2], acc[mi][ni][3]);
            }
        }
        __syncthreads();

        // 128 scanner threads: 2 per query row, 64 cols each, running top-8
        if (tid < 2 * BM) {
            const int row  = tid >> 1;
            const int half = tid & 1;
            const float4* rowp = (const float4*)(Ssf + row * SSW + half * 64);
            #pragma unroll 4
            for (int j = 0; j < 16; j++) {
                float4 v = rowp[j];
                int gi = nbase + half * 64 + j * 4;
                ins8(v.x, gi + 0, tv, ti);
                ins8(v.y, gi + 1, tv, ti);
                ins8(v.z, gi + 2, tv, ti);
                ins8(v.w, gi + 3, tv, ti);
            }
        }
        __syncthreads();   // scan done before next tile's B load overwrites
    }

    if (tid < 2 * BM) {
        const int row  = tid >> 1;
        const int half = tid & 1;
        int q = m0 + row;
        int base = q * CPQ + (split * 2 + half) * CAND;
        #pragma unroll
        for (int i = 0; i < CAND; i++) {
            g_cval[base + i] = tv[i];
            g_cidx[base + i] = ti[i];
        }
    }
}

// ---------------- K3: merge -> exact rescore -> outputs ---------------------
__global__ void merge_out_kernel(const float* __restrict__ Q,
                                 const float* __restrict__ Kx,
                                 const float* __restrict__ values,
                                 const float* __restrict__ errors,
                                 const float* __restrict__ ages,
                                 float* __restrict__ outC,
                                 float* __restrict__ outE,
                                 float* __restrict__ outS,
                                 float* __restrict__ outA, int V) {
    __shared__ float sv[CPQ];
    __shared__ int   si[CPQ];
    __shared__ float b16v[RESC];
    __shared__ int   b16i[RESC];
    __shared__ float se[RESC];
    __shared__ int   bi[TOPK];
    const int q = blockIdx.x;
    const int tid = threadIdx.x;
    const int wid = tid >> 5;
    const int lane = tid & 31;

    sv[tid] = g_cval[q * CPQ + tid];
    si[tid] = g_cidx[q * CPQ + tid];
    __syncthreads();

    if (tid == 0) {   // serial approx top-16 of 256
        for (int i = 0; i < RESC; i++) { b16v[i] = -INFINITY; b16i[i] = 0; }
        for (int i = 0; i < CPQ; i++) {
            float v = sv[i];
            if (v > b16v[RESC - 1]) {
                b16v[RESC - 1] = v; b16i[RESC - 1] = si[i];
                for (int p = RESC - 1; p > 0 && b16v[p] > b16v[p - 1]; p--) {
                    float f = b16v[p - 1]; b16v[p - 1] = b16v[p]; b16v[p] = f;
                    int   g = b16i[p - 1]; b16i[p - 1] = b16i[p]; b16i[p] = g;
                }
            }
        }
    }
    __syncthreads();

    // exact fp32 rescore: 8 warps x 2 candidates
    #pragma unroll
    for (int r = 0; r < 2; r++) {
        int c = wid * 2 + r;
        int idx = b16i[c];
        const float4* qr = (const float4*)(Q + (size_t)q * DDIM);
        const float4* kr = (const float4*)(Kx + (size_t)idx * DDIM);
        float4 qa = qr[lane], qb = qr[lane + 32];
        float4 ka = kr[lane], kb = kr[lane + 32];
        float d = qa.x * ka.x + qa.y * ka.y + qa.z * ka.z + qa.w * ka.w
                + qb.x * kb.x + qb.y * kb.y + qb.z * kb.z + qb.w * kb.w;
        #pragma unroll
        for (int o = 16; o; o >>= 1) d += __shfl_xor_sync(0xffffffffu, d, o);
        if (lane == 0) se[c] = d * g_rq[q] * g_rk[idx];
    }
    __syncthreads();

    if (tid == 0) {   // exact top-5 of 16
        float bv[TOPK]; int bx[TOPK];
        for (int i = 0; i < TOPK; i++) { bv[i] = -INFINITY; bx[i] = 0; }
        for (int i = 0; i < RESC; i++) {
            float v = se[i];
            if (v > bv[TOPK - 1]) {
                bv[TOPK - 1] = v; bx[TOPK - 1] = b16i[i];
                for (int p = TOPK - 1; p > 0 && bv[p] > bv[p - 1]; p--) {
                    float f = bv[p - 1]; bv[p - 1] = bv[p]; bv[p] = f;
                    int   g = bx[p - 1]; bx[p - 1] = bx[p]; bx[p] = g;
                }
            }
        }
        for (int i = 0; i < TOPK; i++) bi[i] = bx[i];
        outE[q] = (errors[bx[0]] + errors[bx[1]] + errors[bx[2]]
                 + errors[bx[3]] + errors[bx[4]]) * 0.2f;
        outS[q] = bv[0];
    }
    __syncthreads();

    for (int c = tid; c < V; c += blockDim.x) {
        float a = 0.f;
        #pragma unroll
        for (int j = 0; j < TOPK; j++)
            a += values[(size_t)bi[j] * V + c];
        outC[(size_t)q * V + c] = a * 0.2f;
    }
    if (tid < TOPK) {
        int ix = bi[tid];
        outA[ix] = ages[ix] + 1.0f;   // identical value under races
    }
}

// ---------------------------------------------------------------------------
extern "C" void kernel_launch(void* const* d_in, const int* in_sizes, int n_in,
                              void* d_out, int out_size) {
    const float* Q  = (const float*)d_in[0];
    const float* Kx = (const float*)d_in[1];
    const float* Vx = (const float*)d_in[2];
    const float* E  = (const float*)d_in[3];
    const float* A  = (const float*)d_in[4];

    const int S = in_sizes[3];
    const int D = in_sizes[1] / S;
    const int V = in_sizes[2] / S;
    const int B = in_sizes[0] / D;

    float* out  = (float*)d_out;
    float* outC = out;
    float* outE = outC + (size_t)B * V;
    float* outS = outE + B;
    float* outA = outS + B;

    float *rq, *rk;
    __nv_bfloat16 *qn, *kn;
    cudaGetSymbolAddress((void**)&rq, g_rq);
    cudaGetSymbolAddress((void**)&rk, g_rk);
    cudaGetSymbolAddress((void**)&qn, g_qn);
    cudaGetSymbolAddress((void**)&kn, g_kn);

    normalize_kernel<<<(B + 7) / 8, 256>>>(Q, rq, qn, B);
    normalize_kernel<<<(S + 7) / 8, 256>>>(Kx, rk, kn, S);
    copy_ages_kernel<<<(S + 255) / 256, 256>>>(A, outA, S);

    cudaFuncSetAttribute(gemm_shortlist_kernel,
                         cudaFuncAttributeMaxDynamicSharedMemorySize, SMEM_SZ);
    dim3 grid(B / BM, NSPLIT);
    gemm_shortlist_kernel<<<grid, 256, SMEM_SZ>>>(S);

    merge_out_kernel<<<B, 256>>>(Q, Kx, Vx, E, A, outC, outE, outS, outA, V);
    (void)n_in; (void)out_size;
}